// round 4
// baseline (speedup 1.0000x reference)
#include <cuda_runtime.h>
#include <cuda_bf16.h>

#define NBLOCKS 2048
#define NTHREADS 256

__constant__ float c_table[28] = {
    0.05f, 0.02f, 0.03f, 0.4f,  0.05f, 0.4f,  0.05f,
    0.05f, 0.05f, 0.05f, 0.05f, 0.3f,  0.05f, 0.45f,
    0.1f,  0.15f, 0.2f,  0.02f, 0.35f, 0.03f, 0.15f,
    1.0f/7.0f, 1.0f/7.0f, 1.0f/7.0f, 1.0f/7.0f, 1.0f/7.0f, 1.0f/7.0f, 1.0f/7.0f
};

__device__ double       g_acc   = 0.0;   // reset by last block each launch
__device__ unsigned int g_count = 0;

__global__ __launch_bounds__(NTHREADS)
void kl_fused_kernel(const float* __restrict__ emo,
                     const int*   __restrict__ tgt,
                     float* __restrict__ out,
                     int B)
{
    __shared__ float s_tn[28];
    __shared__ float s_c[4];
    __shared__ float s_red[NTHREADS / 32];

    const int tid = threadIdx.x;

    if (tid < 4) {
        const float inv = 1.0f / (1.0f + 7.0f * 1e-8f);
        float c = 0.0f;
        #pragma unroll
        for (int j = 0; j < 7; j++) {
            float t = (c_table[tid * 7 + j] + 1e-8f) * inv;
            s_tn[tid * 7 + j] = t;
            c += t * __logf(t);
        }
        s_c[tid] = c;
    }
    __syncthreads();

    float acc = 0.0f;

    // ---- vector mainloop: 4 rows / thread (28 floats = 7 aligned float4) ----
    const int ngroups = B >> 2;
    const int gstride = gridDim.x * blockDim.x;
    const float4* emo4 = (const float4*)emo;
    const int4*   tgt4 = (const int4*)tgt;

    for (int g = blockIdx.x * blockDim.x + tid; g < ngroups; g += gstride) {
        float4 v[7];
        #pragma unroll
        for (int i = 0; i < 7; i++) v[i] = emo4[(size_t)g * 7 + i];
        const float* x = (const float*)v;
        int4 t4 = tgt4[g];
        int ti[4] = {t4.x, t4.y, t4.z, t4.w};

        #pragma unroll
        for (int r = 0; r < 4; r++) {
            float x0 = x[r*7+0], x1 = x[r*7+1], x2 = x[r*7+2], x3 = x[r*7+3];
            float x4 = x[r*7+4], x5 = x[r*7+5], x6 = x[r*7+6];
            int idx = ((unsigned)ti[r] <= 2u) ? ti[r] : 3;

            float m = fmaxf(fmaxf(fmaxf(x0, x1), fmaxf(x2, x3)),
                            fmaxf(fmaxf(x4, x5), x6));

            float s = __expf(x0 - m) + __expf(x1 - m) + __expf(x2 - m)
                    + __expf(x3 - m) + __expf(x4 - m) + __expf(x5 - m)
                    + __expf(x6 - m);

            const float* tn = s_tn + idx * 7;
            float dot = tn[0] * x0;
            dot = fmaf(tn[1], x1, dot);
            dot = fmaf(tn[2], x2, dot);
            dot = fmaf(tn[3], x3, dot);
            dot = fmaf(tn[4], x4, dot);
            dot = fmaf(tn[5], x5, dot);
            dot = fmaf(tn[6], x6, dot);

            acc += s_c[idx] + m + __logf(s) - dot;
        }
    }

    // ---- scalar tail (B % 4 rows), done by global thread 0 ----
    if (blockIdx.x == 0 && tid == 0) {
        for (int row = ngroups << 2; row < B; row++) {
            const float* x = emo + (size_t)row * 7;
            float x0 = x[0], x1 = x[1], x2 = x[2], x3 = x[3];
            float x4 = x[4], x5 = x[5], x6 = x[6];
            int t = tgt[row];
            int idx = ((unsigned)t <= 2u) ? t : 3;
            float m = fmaxf(fmaxf(fmaxf(x0, x1), fmaxf(x2, x3)),
                            fmaxf(fmaxf(x4, x5), x6));
            float s = __expf(x0 - m) + __expf(x1 - m) + __expf(x2 - m)
                    + __expf(x3 - m) + __expf(x4 - m) + __expf(x5 - m)
                    + __expf(x6 - m);
            const float* tn = s_tn + idx * 7;
            float dot = tn[0]*x0 + tn[1]*x1 + tn[2]*x2 + tn[3]*x3
                      + tn[4]*x4 + tn[5]*x5 + tn[6]*x6;
            acc += s_c[idx] + m + __logf(s) - dot;
        }
    }

    // ---- block reduction ----
    #pragma unroll
    for (int o = 16; o > 0; o >>= 1)
        acc += __shfl_down_sync(0xFFFFFFFFu, acc, o);
    if ((tid & 31) == 0) s_red[tid >> 5] = acc;
    __syncthreads();

    if (tid < (NTHREADS / 32)) {
        acc = s_red[tid];
        #pragma unroll
        for (int o = (NTHREADS / 64); o > 0; o >>= 1)
            acc += __shfl_down_sync(0xFFFFFFFFu, acc, o, NTHREADS / 32);
    }

    // ---- grid combine: double atomic + last-block-done writes output ----
    if (tid == 0) {
        atomicAdd(&g_acc, (double)acc);
        __threadfence();
        unsigned int done = atomicAdd(&g_count, 1u);
        if (done == gridDim.x - 1) {
            double total = atomicAdd(&g_acc, 0.0);   // atomic coherent read
            out[0] = (float)(total / (double)B);
            // reset for next graph replay
            g_acc   = 0.0;
            g_count = 0u;
        }
    }
}

extern "C" void kernel_launch(void* const* d_in, const int* in_sizes, int n_in,
                              void* d_out, int out_size)
{
    // inputs: fatigue_logits [B,3] (unused), emotion_logits [B,7], fatigue_targets [B] int32
    const float* emo = (const float*)d_in[1];
    const int*   tgt = (const int*)d_in[2];
    const int B = in_sizes[2];

    kl_fused_kernel<<<NBLOCKS, NTHREADS>>>(emo, tgt, (float*)d_out, B);
}

// round 5
// speedup vs baseline: 1.0010x; 1.0010x over previous
#include <cuda_runtime.h>
#include <cuda_bf16.h>

#define NBLOCKS 2048
#define NTHREADS 256

__constant__ float c_table[28] = {
    0.05f, 0.02f, 0.03f, 0.4f,  0.05f, 0.4f,  0.05f,
    0.05f, 0.05f, 0.05f, 0.05f, 0.3f,  0.05f, 0.45f,
    0.1f,  0.15f, 0.2f,  0.02f, 0.35f, 0.03f, 0.15f,
    1.0f/7.0f, 1.0f/7.0f, 1.0f/7.0f, 1.0f/7.0f, 1.0f/7.0f, 1.0f/7.0f, 1.0f/7.0f
};

__device__ double       g_acc   = 0.0;   // reset by last block each launch
__device__ unsigned int g_count = 0;

__global__ __launch_bounds__(NTHREADS)
void kl_fused_kernel(const float* __restrict__ emo,
                     const int*   __restrict__ tgt,
                     float* __restrict__ out,
                     int B)
{
    __shared__ float s_tn[28];
    __shared__ float s_c[4];
    __shared__ float s_red[NTHREADS / 32];

    const int tid = threadIdx.x;

    if (tid < 4) {
        const float inv = 1.0f / (1.0f + 7.0f * 1e-8f);
        float c = 0.0f;
        #pragma unroll
        for (int j = 0; j < 7; j++) {
            float t = (c_table[tid * 7 + j] + 1e-8f) * inv;
            s_tn[tid * 7 + j] = t;
            c += t * __logf(t);
        }
        s_c[tid] = c;
    }
    __syncthreads();

    float acc = 0.0f;

    // ---- vector mainloop: 4 rows / thread (28 floats = 7 aligned float4) ----
    const int ngroups = B >> 2;
    const int gstride = gridDim.x * blockDim.x;
    const float4* emo4 = (const float4*)emo;
    const int4*   tgt4 = (const int4*)tgt;

    for (int g = blockIdx.x * blockDim.x + tid; g < ngroups; g += gstride) {
        float4 v[7];
        #pragma unroll
        for (int i = 0; i < 7; i++) v[i] = emo4[(size_t)g * 7 + i];
        const float* x = (const float*)v;
        int4 t4 = tgt4[g];
        int ti[4] = {t4.x, t4.y, t4.z, t4.w};

        #pragma unroll
        for (int r = 0; r < 4; r++) {
            float x0 = x[r*7+0], x1 = x[r*7+1], x2 = x[r*7+2], x3 = x[r*7+3];
            float x4 = x[r*7+4], x5 = x[r*7+5], x6 = x[r*7+6];
            int idx = ((unsigned)ti[r] <= 2u) ? ti[r] : 3;

            float m = fmaxf(fmaxf(fmaxf(x0, x1), fmaxf(x2, x3)),
                            fmaxf(fmaxf(x4, x5), x6));

            float s = __expf(x0 - m) + __expf(x1 - m) + __expf(x2 - m)
                    + __expf(x3 - m) + __expf(x4 - m) + __expf(x5 - m)
                    + __expf(x6 - m);

            const float* tn = s_tn + idx * 7;
            float dot = tn[0] * x0;
            dot = fmaf(tn[1], x1, dot);
            dot = fmaf(tn[2], x2, dot);
            dot = fmaf(tn[3], x3, dot);
            dot = fmaf(tn[4], x4, dot);
            dot = fmaf(tn[5], x5, dot);
            dot = fmaf(tn[6], x6, dot);

            acc += s_c[idx] + m + __logf(s) - dot;
        }
    }

    // ---- scalar tail (B % 4 rows), done by global thread 0 ----
    if (blockIdx.x == 0 && tid == 0) {
        for (int row = ngroups << 2; row < B; row++) {
            const float* x = emo + (size_t)row * 7;
            float x0 = x[0], x1 = x[1], x2 = x[2], x3 = x[3];
            float x4 = x[4], x5 = x[5], x6 = x[6];
            int t = tgt[row];
            int idx = ((unsigned)t <= 2u) ? t : 3;
            float m = fmaxf(fmaxf(fmaxf(x0, x1), fmaxf(x2, x3)),
                            fmaxf(fmaxf(x4, x5), x6));
            float s = __expf(x0 - m) + __expf(x1 - m) + __expf(x2 - m)
                    + __expf(x3 - m) + __expf(x4 - m) + __expf(x5 - m)
                    + __expf(x6 - m);
            const float* tn = s_tn + idx * 7;
            float dot = tn[0]*x0 + tn[1]*x1 + tn[2]*x2 + tn[3]*x3
                      + tn[4]*x4 + tn[5]*x5 + tn[6]*x6;
            acc += s_c[idx] + m + __logf(s) - dot;
        }
    }

    // ---- block reduction ----
    #pragma unroll
    for (int o = 16; o > 0; o >>= 1)
        acc += __shfl_down_sync(0xFFFFFFFFu, acc, o);
    if ((tid & 31) == 0) s_red[tid >> 5] = acc;
    __syncthreads();

    if (tid < (NTHREADS / 32)) {
        acc = s_red[tid];
        #pragma unroll
        for (int o = (NTHREADS / 64); o > 0; o >>= 1)
            acc += __shfl_down_sync(0xFFFFFFFFu, acc, o, NTHREADS / 32);
    }

    // ---- grid combine: double atomic + last-block-done writes output ----
    if (tid == 0) {
        atomicAdd(&g_acc, (double)acc);
        __threadfence();
        unsigned int done = atomicAdd(&g_count, 1u);
        if (done == gridDim.x - 1) {
            double total = atomicAdd(&g_acc, 0.0);   // atomic coherent read
            out[0] = (float)(total / (double)B);
            // reset for next graph replay
            g_acc   = 0.0;
            g_count = 0u;
        }
    }
}

extern "C" void kernel_launch(void* const* d_in, const int* in_sizes, int n_in,
                              void* d_out, int out_size)
{
    // inputs: fatigue_logits [B,3] (unused), emotion_logits [B,7], fatigue_targets [B] int32
    const float* emo = (const float*)d_in[1];
    const int*   tgt = (const int*)d_in[2];
    const int B = in_sizes[2];

    kl_fused_kernel<<<NBLOCKS, NTHREADS>>>(emo, tgt, (float*)d_out, B);
}

// round 6
// speedup vs baseline: 1.0609x; 1.0598x over previous
#include <cuda_runtime.h>
#include <cuda_bf16.h>

#define NBLOCKS 2048
#define NTHREADS 256

__constant__ float c_table[28] = {
    0.05f, 0.02f, 0.03f, 0.4f,  0.05f, 0.4f,  0.05f,
    0.05f, 0.05f, 0.05f, 0.05f, 0.3f,  0.05f, 0.45f,
    0.1f,  0.15f, 0.2f,  0.02f, 0.35f, 0.03f, 0.15f,
    1.0f/7.0f, 1.0f/7.0f, 1.0f/7.0f, 1.0f/7.0f, 1.0f/7.0f, 1.0f/7.0f, 1.0f/7.0f
};

__device__ double       g_acc   = 0.0;   // reset by last block each launch
__device__ unsigned int g_count = 0;

__global__ __launch_bounds__(NTHREADS)
void kl_fused_kernel(const float* __restrict__ emo,
                     const int*   __restrict__ tgt,
                     float* __restrict__ out,
                     int B)
{
    __shared__ float s_tn[28];
    __shared__ float s_c[4];
    __shared__ float s_red[NTHREADS / 32];

    const int tid = threadIdx.x;

    if (tid < 4) {
        const float inv = 1.0f / (1.0f + 7.0f * 1e-8f);
        float c = 0.0f;
        #pragma unroll
        for (int j = 0; j < 7; j++) {
            float t = (c_table[tid * 7 + j] + 1e-8f) * inv;
            s_tn[tid * 7 + j] = t;
            c += t * __logf(t);
        }
        s_c[tid] = c;
    }
    __syncthreads();

    float acc = 0.0f;
    const int stride = gridDim.x * blockDim.x;

    // Scalar row loop: 8 independent loads per iteration (7 floats + 1 int),
    // each warp-coalesced — high MLP at low register cost.
    for (int row = blockIdx.x * blockDim.x + tid; row < B; row += stride) {
        const float* x = emo + (size_t)row * 7;
        float x0 = x[0], x1 = x[1], x2 = x[2], x3 = x[3];
        float x4 = x[4], x5 = x[5], x6 = x[6];
        int t = tgt[row];
        int idx = ((unsigned)t <= 2u) ? t : 3;

        float m = fmaxf(fmaxf(fmaxf(x0, x1), fmaxf(x2, x3)),
                        fmaxf(fmaxf(x4, x5), x6));

        float s = __expf(x0 - m) + __expf(x1 - m) + __expf(x2 - m)
                + __expf(x3 - m) + __expf(x4 - m) + __expf(x5 - m)
                + __expf(x6 - m);

        const float* tn = s_tn + idx * 7;
        float dot = tn[0] * x0;
        dot = fmaf(tn[1], x1, dot);
        dot = fmaf(tn[2], x2, dot);
        dot = fmaf(tn[3], x3, dot);
        dot = fmaf(tn[4], x4, dot);
        dot = fmaf(tn[5], x5, dot);
        dot = fmaf(tn[6], x6, dot);

        // KL_row = C[idx] + m + log(s) - dot   (sum_j t_j == 1)
        acc += s_c[idx] + m + __logf(s) - dot;
    }

    // ---- block reduction ----
    #pragma unroll
    for (int o = 16; o > 0; o >>= 1)
        acc += __shfl_down_sync(0xFFFFFFFFu, acc, o);
    if ((tid & 31) == 0) s_red[tid >> 5] = acc;
    __syncthreads();

    if (tid < (NTHREADS / 32)) {
        acc = s_red[tid];
        #pragma unroll
        for (int o = (NTHREADS / 64); o > 0; o >>= 1)
            acc += __shfl_down_sync(0xFFFFFFFFu, acc, o, NTHREADS / 32);
    }

    // ---- grid combine: double atomic + last-block-done writes output ----
    if (tid == 0) {
        atomicAdd(&g_acc, (double)acc);
        __threadfence();
        unsigned int done = atomicAdd(&g_count, 1u);
        if (done == gridDim.x - 1) {
            double total = atomicAdd(&g_acc, 0.0);   // atomic coherent read
            out[0] = (float)(total / (double)B);
            // reset for next graph replay
            g_acc   = 0.0;
            g_count = 0u;
        }
    }
}

extern "C" void kernel_launch(void* const* d_in, const int* in_sizes, int n_in,
                              void* d_out, int out_size)
{
    // inputs: fatigue_logits [B,3] (unused), emotion_logits [B,7], fatigue_targets [B] int32
    const float* emo = (const float*)d_in[1];
    const int*   tgt = (const int*)d_in[2];
    const int B = in_sizes[2];

    kl_fused_kernel<<<NBLOCKS, NTHREADS>>>(emo, tgt, (float*)d_out, B);
}

// round 7
// speedup vs baseline: 1.0702x; 1.0088x over previous
#include <cuda_runtime.h>
#include <cuda_bf16.h>

#define NBLOCKS (148 * 8)
#define NTHREADS 256

__constant__ float c_table[28] = {
    0.05f, 0.02f, 0.03f, 0.4f,  0.05f, 0.4f,  0.05f,
    0.05f, 0.05f, 0.05f, 0.05f, 0.3f,  0.05f, 0.45f,
    0.1f,  0.15f, 0.2f,  0.02f, 0.35f, 0.03f, 0.15f,
    1.0f/7.0f, 1.0f/7.0f, 1.0f/7.0f, 1.0f/7.0f, 1.0f/7.0f, 1.0f/7.0f, 1.0f/7.0f
};

__device__ double       g_acc   = 0.0;   // reset by last block each launch
__device__ unsigned int g_count = 0;

__device__ __forceinline__ float row_kl(float x0, float x1, float x2, float x3,
                                        float x4, float x5, float x6,
                                        int idx, const float* s_tn, const float* s_c)
{
    float m = fmaxf(fmaxf(fmaxf(x0, x1), fmaxf(x2, x3)),
                    fmaxf(fmaxf(x4, x5), x6));
    float s = __expf(x0 - m) + __expf(x1 - m) + __expf(x2 - m)
            + __expf(x3 - m) + __expf(x4 - m) + __expf(x5 - m)
            + __expf(x6 - m);
    const float* tn = s_tn + idx * 7;
    float dot = tn[0] * x0;
    dot = fmaf(tn[1], x1, dot);
    dot = fmaf(tn[2], x2, dot);
    dot = fmaf(tn[3], x3, dot);
    dot = fmaf(tn[4], x4, dot);
    dot = fmaf(tn[5], x5, dot);
    dot = fmaf(tn[6], x6, dot);
    return s_c[idx] + m + __logf(s) - dot;
}

__global__ __launch_bounds__(NTHREADS)
void kl_fused_kernel(const float* __restrict__ emo,
                     const int*   __restrict__ tgt,
                     float* __restrict__ out,
                     int B)
{
    __shared__ float s_tn[28];
    __shared__ float s_c[4];
    __shared__ float s_red[NTHREADS / 32];

    const int tid = threadIdx.x;

    if (tid < 4) {
        const float inv = 1.0f / (1.0f + 7.0f * 1e-8f);
        float c = 0.0f;
        #pragma unroll
        for (int j = 0; j < 7; j++) {
            float t = (c_table[tid * 7 + j] + 1e-8f) * inv;
            s_tn[tid * 7 + j] = t;
            c += t * __logf(t);
        }
        s_c[tid] = c;
    }
    __syncthreads();

    float acc = 0.0f;

    // ---- 2 rows per thread per iteration: 16 independent loads batched
    //      before any math (doubles bytes-in-flight vs 1-row loop). ----
    const int npairs  = B >> 1;
    const int gstride = gridDim.x * blockDim.x;

    for (int p = blockIdx.x * blockDim.x + tid; p < npairs; p += gstride) {
        const float* xa = emo + (size_t)(2 * p) * 7;
        const float* xb = xa + 7;

        float a0 = xa[0], a1 = xa[1], a2 = xa[2], a3 = xa[3];
        float a4 = xa[4], a5 = xa[5], a6 = xa[6];
        float b0 = xb[0], b1 = xb[1], b2 = xb[2], b3 = xb[3];
        float b4 = xb[4], b5 = xb[5], b6 = xb[6];
        int ta = tgt[2 * p];
        int tb = tgt[2 * p + 1];

        int ia = ((unsigned)ta <= 2u) ? ta : 3;
        int ib = ((unsigned)tb <= 2u) ? tb : 3;

        acc += row_kl(a0, a1, a2, a3, a4, a5, a6, ia, s_tn, s_c);
        acc += row_kl(b0, b1, b2, b3, b4, b5, b6, ib, s_tn, s_c);
    }

    // ---- odd tail row (B % 2), global thread 0 ----
    if ((B & 1) && blockIdx.x == 0 && tid == 0) {
        const float* x = emo + (size_t)(B - 1) * 7;
        int t = tgt[B - 1];
        int idx = ((unsigned)t <= 2u) ? t : 3;
        acc += row_kl(x[0], x[1], x[2], x[3], x[4], x[5], x[6], idx, s_tn, s_c);
    }

    // ---- block reduction ----
    #pragma unroll
    for (int o = 16; o > 0; o >>= 1)
        acc += __shfl_down_sync(0xFFFFFFFFu, acc, o);
    if ((tid & 31) == 0) s_red[tid >> 5] = acc;
    __syncthreads();

    if (tid < (NTHREADS / 32)) {
        acc = s_red[tid];
        #pragma unroll
        for (int o = (NTHREADS / 64); o > 0; o >>= 1)
            acc += __shfl_down_sync(0xFFFFFFFFu, acc, o, NTHREADS / 32);
    }

    // ---- grid combine: double atomic + last-block-done writes output ----
    if (tid == 0) {
        atomicAdd(&g_acc, (double)acc);
        __threadfence();
        unsigned int done = atomicAdd(&g_count, 1u);
        if (done == gridDim.x - 1) {
            double total = atomicAdd(&g_acc, 0.0);   // atomic coherent read
            out[0] = (float)(total / (double)B);
            g_acc   = 0.0;
            g_count = 0u;
        }
    }
}

extern "C" void kernel_launch(void* const* d_in, const int* in_sizes, int n_in,
                              void* d_out, int out_size)
{
    // inputs: fatigue_logits [B,3] (unused), emotion_logits [B,7], fatigue_targets [B] int32
    const float* emo = (const float*)d_in[1];
    const int*   tgt = (const int*)d_in[2];
    const int B = in_sizes[2];

    kl_fused_kernel<<<NBLOCKS, NTHREADS>>>(emo, tgt, (float*)d_out, B);
}